// round 14
// baseline (speedup 1.0000x reference)
#include <cuda_runtime.h>

#define NDIM 4096

// Inter-layer spike vectors (scratch via __device__ globals — no allocation).
__device__ float g_enc[NDIM];
__device__ float g_s0[NDIM];
__device__ float g_s1[NDIM];

// Rate-coding encoder: enc_i = (u_i < x_i) ? 1 : 0. Tiny; hidden under
// layer0's PDL prefetch ramp.
__global__ void enc_k(const float* __restrict__ x, const float* __restrict__ u) {
    int i = blockIdx.x * blockDim.x + threadIdx.x;
    if (i < NDIM) g_enc[i] = (u[i] < x[i]) ? 1.0f : 0.0f;
}

// Masked matvec + threshold, PDL consumer. One row per block (grid 4096),
// 256 threads. The ENTIRE 32 KB W/M row pair (spike-independent) is issued
// with plain LDG.128 BEFORE cudaGridDependencySynchronize(), so early-launched
// blocks keep DRAM saturated across the kernel boundary. Steady-state loop is
// the R1 form (plain loads — fastest measured, 72.4% DRAM).
//  IN : 0 -> g_enc, 1 -> g_s0, 2 -> g_s1
//  OUT: 0 -> g_s0,  1 -> g_s1, 2 -> out[row] = spk / T
template<int IN, int OUT>
__global__ __launch_bounds__(256) void layer_k(const float* __restrict__ W,
                                               const float* __restrict__ M,
                                               const int* __restrict__ Tp,
                                               float* __restrict__ out) {
    const int row = blockIdx.x;
    const float4* __restrict__ w4 = (const float4*)W + (size_t)row * (NDIM / 4);
    const float4* __restrict__ m4 = (const float4*)M + (size_t)row * (NDIM / 4);

    const int i0 = threadIdx.x;
    const int i1 = threadIdx.x + 256;
    const int i2 = threadIdx.x + 512;
    const int i3 = threadIdx.x + 768;

    // All spike-independent DRAM loads in flight across the PDL edge.
    const float4 w0 = w4[i0];
    const float4 m0 = m4[i0];
    const float4 w1 = w4[i1];
    const float4 m1 = m4[i1];
    const float4 w2 = w4[i2];
    const float4 m2 = m4[i2];
    const float4 w3 = w4[i3];
    const float4 m3 = m4[i3];

    // Wait for the previous grid (spike/enc vector becomes valid).
    cudaGridDependencySynchronize();

    const float* s = (IN == 0) ? g_enc : (IN == 1) ? g_s0 : g_s1;
    const float4* __restrict__ s4 = (const float4*)s;
    const float4 v0 = s4[i0];
    const float4 v1 = s4[i1];
    const float4 v2 = s4[i2];
    const float4 v3 = s4[i3];

    float a0 = 0.0f, a1 = 0.0f;
    a0 = fmaf(w0.x * m0.x, v0.x, a0); a0 = fmaf(w0.y * m0.y, v0.y, a0);
    a0 = fmaf(w0.z * m0.z, v0.z, a0); a0 = fmaf(w0.w * m0.w, v0.w, a0);
    a1 = fmaf(w1.x * m1.x, v1.x, a1); a1 = fmaf(w1.y * m1.y, v1.y, a1);
    a1 = fmaf(w1.z * m1.z, v1.z, a1); a1 = fmaf(w1.w * m1.w, v1.w, a1);
    a0 = fmaf(w2.x * m2.x, v2.x, a0); a0 = fmaf(w2.y * m2.y, v2.y, a0);
    a0 = fmaf(w2.z * m2.z, v2.z, a0); a0 = fmaf(w2.w * m2.w, v2.w, a0);
    a1 = fmaf(w3.x * m3.x, v3.x, a1); a1 = fmaf(w3.y * m3.y, v3.y, a1);
    a1 = fmaf(w3.z * m3.z, v3.z, a1); a1 = fmaf(w3.w * m3.w, v3.w, a1);

    float acc = a0 + a1;
#pragma unroll
    for (int o = 16; o; o >>= 1) acc += __shfl_xor_sync(0xffffffffu, acc, o);

    __shared__ float sm[8];
    if ((threadIdx.x & 31) == 0) sm[threadIdx.x >> 5] = acc;
    __syncthreads();
    if (threadIdx.x == 0) {
        float t = 0.0f;
#pragma unroll
        for (int i = 0; i < 8; i++) t += sm[i];
        const float spk = (t > 1.0f) ? 1.0f : 0.0f;   // THRESH = 1.0
        if (OUT == 0)      g_s0[row] = spk;
        else if (OUT == 1) g_s1[row] = spk;
        else {
            const int T = Tp ? *Tp : 128;
            out[row] = spk / (float)T;                // spikes only at t=0
        }
    }
}

extern "C" void kernel_launch(void* const* d_in, const int* in_sizes, int n_in,
                              void* d_out, int out_size) {
    const float* x  = (const float*)d_in[0];
    const float* u  = (const float*)d_in[1];
    const float* W0 = (const float*)d_in[2];
    const float* W1 = (const float*)d_in[3];
    const float* W2 = (const float*)d_in[4];
    const float* M0 = (const float*)d_in[5];
    const float* M1 = (const float*)d_in[6];
    const float* M2 = (const float*)d_in[7];
    const int*   T  = (n_in > 8) ? (const int*)d_in[8] : nullptr;
    float* out = (float*)d_out;

    enc_k<<<NDIM / 256, 256>>>(x, u);

    cudaLaunchAttribute attr[1];
    attr[0].id = cudaLaunchAttributeProgrammaticStreamSerialization;
    attr[0].val.programmaticStreamSerializationAllowed = 1;

    cudaLaunchConfig_t cfg = {};
    cfg.gridDim  = dim3(NDIM, 1, 1);
    cfg.blockDim = dim3(256, 1, 1);
    cfg.dynamicSmemBytes = 0;
    cfg.stream = 0;
    cfg.attrs = attr;
    cfg.numAttrs = 1;

    cudaLaunchKernelEx(&cfg, layer_k<0, 0>, W0, M0, (const int*)nullptr,
                       (float*)nullptr);
    cudaLaunchKernelEx(&cfg, layer_k<1, 1>, W1, M1, (const int*)nullptr,
                       (float*)nullptr);
    cudaLaunchKernelEx(&cfg, layer_k<2, 2>, W2, M2, T, out);
}

// round 15
// speedup vs baseline: 1.0979x; 1.0979x over previous
#include <cuda_runtime.h>

#define NDIM 4096

// Inter-layer spike vectors (scratch via __device__ globals — no allocation).
__device__ float g_enc[NDIM];
__device__ float g_s0[NDIM];
__device__ float g_s1[NDIM];

// Rate-coding encoder: enc_i = (u_i < x_i) ? 1 : 0. Tiny; its latency hides
// under layer0's PDL prefetch ramp.
__global__ void enc_k(const float* __restrict__ x, const float* __restrict__ u) {
    int i = blockIdx.x * blockDim.x + threadIdx.x;
    if (i < NDIM) g_enc[i] = (u[i] < x[i]) ? 1.0f : 0.0f;
}

// Masked matvec + threshold, PDL consumer. One row per block (grid 4096),
// 256 threads. The ENTIRE 32 KB W/M row pair (spike-independent) is issued
// with __ldcs (evict-first streaming — keeps L1 clean AND keeps the batch
// hoisted above the sync) BEFORE cudaGridDependencySynchronize().
//  IN : 0 -> g_enc, 1 -> g_s0, 2 -> g_s1
//  OUT: 0 -> g_s0,  1 -> g_s1, 2 -> out[row] = spk / T
template<int IN, int OUT>
__global__ __launch_bounds__(256) void layer_k(const float* __restrict__ W,
                                               const float* __restrict__ M,
                                               const int* __restrict__ Tp,
                                               float* __restrict__ out) {
    const int row = blockIdx.x;
    const float4* __restrict__ w4 = (const float4*)W + (size_t)row * (NDIM / 4);
    const float4* __restrict__ m4 = (const float4*)M + (size_t)row * (NDIM / 4);

    const int i0 = threadIdx.x;
    const int i1 = threadIdx.x + 256;
    const int i2 = threadIdx.x + 512;
    const int i3 = threadIdx.x + 768;

    // All spike-independent DRAM loads in flight across the PDL edge.
    const float4 w0 = __ldcs(w4 + i0);
    const float4 m0 = __ldcs(m4 + i0);
    const float4 w1 = __ldcs(w4 + i1);
    const float4 m1 = __ldcs(m4 + i1);
    const float4 w2 = __ldcs(w4 + i2);
    const float4 m2 = __ldcs(m4 + i2);
    const float4 w3 = __ldcs(w4 + i3);
    const float4 m3 = __ldcs(m4 + i3);

    // Wait for the previous grid (spike/enc vector becomes valid).
    cudaGridDependencySynchronize();

    const float* s = (IN == 0) ? g_enc : (IN == 1) ? g_s0 : g_s1;
    const float4* __restrict__ s4 = (const float4*)s;
    const float4 v0 = __ldg(s4 + i0);
    const float4 v1 = __ldg(s4 + i1);
    const float4 v2 = __ldg(s4 + i2);
    const float4 v3 = __ldg(s4 + i3);

    float a0 = 0.0f, a1 = 0.0f;
    a0 = fmaf(w0.x * m0.x, v0.x, a0); a0 = fmaf(w0.y * m0.y, v0.y, a0);
    a0 = fmaf(w0.z * m0.z, v0.z, a0); a0 = fmaf(w0.w * m0.w, v0.w, a0);
    a1 = fmaf(w1.x * m1.x, v1.x, a1); a1 = fmaf(w1.y * m1.y, v1.y, a1);
    a1 = fmaf(w1.z * m1.z, v1.z, a1); a1 = fmaf(w1.w * m1.w, v1.w, a1);
    a0 = fmaf(w2.x * m2.x, v2.x, a0); a0 = fmaf(w2.y * m2.y, v2.y, a0);
    a0 = fmaf(w2.z * m2.z, v2.z, a0); a0 = fmaf(w2.w * m2.w, v2.w, a0);
    a1 = fmaf(w3.x * m3.x, v3.x, a1); a1 = fmaf(w3.y * m3.y, v3.y, a1);
    a1 = fmaf(w3.z * m3.z, v3.z, a1); a1 = fmaf(w3.w * m3.w, v3.w, a1);

    float acc = a0 + a1;
#pragma unroll
    for (int o = 16; o; o >>= 1) acc += __shfl_xor_sync(0xffffffffu, acc, o);

    __shared__ float sm[8];
    if ((threadIdx.x & 31) == 0) sm[threadIdx.x >> 5] = acc;
    __syncthreads();
    if (threadIdx.x == 0) {
        float t = 0.0f;
#pragma unroll
        for (int i = 0; i < 8; i++) t += sm[i];
        const float spk = (t > 1.0f) ? 1.0f : 0.0f;   // THRESH = 1.0
        if (OUT == 0)      g_s0[row] = spk;
        else if (OUT == 1) g_s1[row] = spk;
        else {
            const int T = Tp ? *Tp : 128;
            out[row] = spk / (float)T;                // spikes only at t=0
        }
    }
}

extern "C" void kernel_launch(void* const* d_in, const int* in_sizes, int n_in,
                              void* d_out, int out_size) {
    const float* x  = (const float*)d_in[0];
    const float* u  = (const float*)d_in[1];
    const float* W0 = (const float*)d_in[2];
    const float* W1 = (const float*)d_in[3];
    const float* W2 = (const float*)d_in[4];
    const float* M0 = (const float*)d_in[5];
    const float* M1 = (const float*)d_in[6];
    const float* M2 = (const float*)d_in[7];
    const int*   T  = (n_in > 8) ? (const int*)d_in[8] : nullptr;
    float* out = (float*)d_out;

    enc_k<<<NDIM / 256, 256>>>(x, u);

    cudaLaunchAttribute attr[1];
    attr[0].id = cudaLaunchAttributeProgrammaticStreamSerialization;
    attr[0].val.programmaticStreamSerializationAllowed = 1;

    cudaLaunchConfig_t cfg = {};
    cfg.gridDim  = dim3(NDIM, 1, 1);
    cfg.blockDim = dim3(256, 1, 1);
    cfg.dynamicSmemBytes = 0;
    cfg.stream = 0;
    cfg.attrs = attr;
    cfg.numAttrs = 1;

    cudaLaunchKernelEx(&cfg, layer_k<0, 0>, W0, M0, (const int*)nullptr,
                       (float*)nullptr);
    cudaLaunchKernelEx(&cfg, layer_k<1, 1>, W1, M1, (const int*)nullptr,
                       (float*)nullptr);
    cudaLaunchKernelEx(&cfg, layer_k<2, 2>, W2, M2, T, out);
}

// round 17
// speedup vs baseline: 1.1043x; 1.0058x over previous
#include <cuda_runtime.h>

#define NDIM 4096

// Inter-layer spike vectors (scratch via __device__ globals — no allocation).
__device__ float g_enc[NDIM];
__device__ float g_s0[NDIM];
__device__ float g_s1[NDIM];

// Rate-coding encoder: enc_i = (u_i < x_i) ? 1 : 0.
__global__ void enc_k(const float* __restrict__ x, const float* __restrict__ u) {
    int i = blockIdx.x * blockDim.x + threadIdx.x;
    if (i < NDIM) g_enc[i] = (u[i] < x[i]) ? 1.0f : 0.0f;
}

// Streaming 128-bit load as VOLATILE asm: ptxas cannot sink it past the
// (volatile) griddepcontrol.wait — guarantees the prefetch is actually
// issued before the PDL sync.
__device__ __forceinline__ float4 ldcs128_v(const float4* p) {
    float4 r;
    asm volatile("ld.global.cs.v4.f32 {%0,%1,%2,%3}, [%4];"
                 : "=f"(r.x), "=f"(r.y), "=f"(r.z), "=f"(r.w)
                 : "l"(p));
    return r;
}

// Masked matvec + threshold, PDL consumer. One row per block (grid 4096),
// 256 threads. The ENTIRE 32 KB W/M row pair is force-issued (volatile asm)
// BEFORE cudaGridDependencySynchronize(), so early-launched blocks keep DRAM
// saturated across the kernel boundary.
//  IN : 0 -> g_enc, 1 -> g_s0, 2 -> g_s1
//  OUT: 0 -> g_s0,  1 -> g_s1, 2 -> out[row] = spk / T
template<int IN, int OUT>
__global__ __launch_bounds__(256) void layer_k(const float* __restrict__ W,
                                               const float* __restrict__ M,
                                               const int* __restrict__ Tp,
                                               float* __restrict__ out) {
    const int row = blockIdx.x;
    const float4* __restrict__ w4 = (const float4*)W + (size_t)row * (NDIM / 4);
    const float4* __restrict__ m4 = (const float4*)M + (size_t)row * (NDIM / 4);

    const int i0 = threadIdx.x;
    const int i1 = threadIdx.x + 256;
    const int i2 = threadIdx.x + 512;
    const int i3 = threadIdx.x + 768;

    // All spike-independent DRAM loads, pinned above the PDL edge.
    const float4 w0 = ldcs128_v(w4 + i0);
    const float4 m0 = ldcs128_v(m4 + i0);
    const float4 w1 = ldcs128_v(w4 + i1);
    const float4 m1 = ldcs128_v(m4 + i1);
    const float4 w2 = ldcs128_v(w4 + i2);
    const float4 m2 = ldcs128_v(m4 + i2);
    const float4 w3 = ldcs128_v(w4 + i3);
    const float4 m3 = ldcs128_v(m4 + i3);

    // Wait for the previous grid (spike/enc vector becomes valid).
    cudaGridDependencySynchronize();

    const float* s = (IN == 0) ? g_enc : (IN == 1) ? g_s0 : g_s1;
    const float4* __restrict__ s4 = (const float4*)s;
    const float4 v0 = __ldg(s4 + i0);
    const float4 v1 = __ldg(s4 + i1);
    const float4 v2 = __ldg(s4 + i2);
    const float4 v3 = __ldg(s4 + i3);

    float a0 = 0.0f, a1 = 0.0f;
    a0 = fmaf(w0.x * m0.x, v0.x, a0); a0 = fmaf(w0.y * m0.y, v0.y, a0);
    a0 = fmaf(w0.z * m0.z, v0.z, a0); a0 = fmaf(w0.w * m0.w, v0.w, a0);
    a1 = fmaf(w1.x * m1.x, v1.x, a1); a1 = fmaf(w1.y * m1.y, v1.y, a1);
    a1 = fmaf(w1.z * m1.z, v1.z, a1); a1 = fmaf(w1.w * m1.w, v1.w, a1);
    a0 = fmaf(w2.x * m2.x, v2.x, a0); a0 = fmaf(w2.y * m2.y, v2.y, a0);
    a0 = fmaf(w2.z * m2.z, v2.z, a0); a0 = fmaf(w2.w * m2.w, v2.w, a0);
    a1 = fmaf(w3.x * m3.x, v3.x, a1); a1 = fmaf(w3.y * m3.y, v3.y, a1);
    a1 = fmaf(w3.z * m3.z, v3.z, a1); a1 = fmaf(w3.w * m3.w, v3.w, a1);

    float acc = a0 + a1;
#pragma unroll
    for (int o = 16; o; o >>= 1) acc += __shfl_xor_sync(0xffffffffu, acc, o);

    __shared__ float sm[8];
    if ((threadIdx.x & 31) == 0) sm[threadIdx.x >> 5] = acc;
    __syncthreads();
    if (threadIdx.x == 0) {
        float t = 0.0f;
#pragma unroll
        for (int i = 0; i < 8; i++) t += sm[i];
        const float spk = (t > 1.0f) ? 1.0f : 0.0f;   // THRESH = 1.0
        if (OUT == 0)      g_s0[row] = spk;
        else if (OUT == 1) g_s1[row] = spk;
        else {
            const int T = Tp ? *Tp : 128;
            out[row] = spk / (float)T;                // spikes only at t=0
        }
    }
}

extern "C" void kernel_launch(void* const* d_in, const int* in_sizes, int n_in,
                              void* d_out, int out_size) {
    const float* x  = (const float*)d_in[0];
    const float* u  = (const float*)d_in[1];
    const float* W0 = (const float*)d_in[2];
    const float* W1 = (const float*)d_in[3];
    const float* W2 = (const float*)d_in[4];
    const float* M0 = (const float*)d_in[5];
    const float* M1 = (const float*)d_in[6];
    const float* M2 = (const float*)d_in[7];
    const int*   T  = (n_in > 8) ? (const int*)d_in[8] : nullptr;
    float* out = (float*)d_out;

    enc_k<<<NDIM / 256, 256>>>(x, u);

    cudaLaunchAttribute attr[1];
    attr[0].id = cudaLaunchAttributeProgrammaticStreamSerialization;
    attr[0].val.programmaticStreamSerializationAllowed = 1;

    cudaLaunchConfig_t cfg = {};
    cfg.gridDim  = dim3(NDIM, 1, 1);
    cfg.blockDim = dim3(256, 1, 1);
    cfg.dynamicSmemBytes = 0;
    cfg.stream = 0;
    cfg.attrs = attr;
    cfg.numAttrs = 1;

    cudaLaunchKernelEx(&cfg, layer_k<0, 0>, W0, M0, (const int*)nullptr,
                       (float*)nullptr);
    cudaLaunchKernelEx(&cfg, layer_k<1, 1>, W1, M1, (const int*)nullptr,
                       (float*)nullptr);
    cudaLaunchKernelEx(&cfg, layer_k<2, 2>, W2, M2, T, out);
}